// round 13
// baseline (speedup 1.0000x reference)
#include <cuda_runtime.h>

// SpikeLayer: T=16 timesteps, per-step batch B=512, features D=8192.
// For each (b, d): V += x[t]; if |V| > 1 -> V = 0; out[t] = V.
//
// Final form (R12): memory-shape converged. 512 MiB irreducible R+W traffic,
// DRAM-ceiling bound (~81% dram__cycles_active across all variants).
// Winning layout: one-pass float4/thread, GRP=4 load/compute/store batches,
// streaming (.cs) hints, full grid. R12 tweak: 512-thread CTAs (2048 blocks)
// for slightly larger contiguous per-CTA footprint per t-slab.

#define TT 16
#define BB 512
#define DD 8192
#define STRIDE4 ((BB * DD) / 4)   // float4 per timestep slab = 1,048,576
#define GRP 4
#define TPB 512

__global__ __launch_bounds__(TPB) void spike_kernel(
    const float4* __restrict__ in, float4* __restrict__ out)
{
    const unsigned idx = blockIdx.x * (unsigned)TPB + threadIdx.x;
    const float4* __restrict__ p = in  + idx;
    float4*       __restrict__ q = out + idx;

    float4 V = make_float4(0.f, 0.f, 0.f, 0.f);
    float4 x[GRP];

#pragma unroll
    for (int g = 0; g < TT / GRP; ++g) {
        // Batch 4 streaming loads
#pragma unroll
        for (int t = 0; t < GRP; ++t)
            x[t] = __ldcs(p + (unsigned)(g * GRP + t) * STRIDE4);

        // Dependency chain in registers; overwrite x[] with outputs
#pragma unroll
        for (int t = 0; t < GRP; ++t) {
            V.x += x[t].x;  V.x = (fabsf(V.x) > 1.0f) ? 0.0f : V.x;
            V.y += x[t].y;  V.y = (fabsf(V.y) > 1.0f) ? 0.0f : V.y;
            V.z += x[t].z;  V.z = (fabsf(V.z) > 1.0f) ? 0.0f : V.z;
            V.w += x[t].w;  V.w = (fabsf(V.w) > 1.0f) ? 0.0f : V.w;
            x[t] = V;
        }

        // Batch 4 streaming stores
#pragma unroll
        for (int t = 0; t < GRP; ++t)
            __stcs(q + (unsigned)(g * GRP + t) * STRIDE4, x[t]);
    }
}

extern "C" void kernel_launch(void* const* d_in, const int* in_sizes, int n_in,
                              void* d_out, int out_size)
{
    (void)in_sizes; (void)n_in; (void)out_size;
    const float4* in  = (const float4*)d_in[0];
    float4*       out = (float4*)d_out;

    const int blocks = STRIDE4 / TPB;  // 2048
    spike_kernel<<<blocks, TPB>>>(in, out);
}

// round 14
// speedup vs baseline: 1.0050x; 1.0050x over previous
#include <cuda_runtime.h>

// SpikeLayer: T=16 timesteps, per-step batch B=512, features D=8192.
// For each (b, d): V += x[t]; if |V| > 1 -> V = 0; out[t] = V.
//
// FINAL (R13): converged at the HBM mixed read/write ceiling.
// Evidence across R3-R12: GRP sweep {16,8,4,2} -> {77.5,76.7,75.6,76.7} us;
// TPB {256,512} -> {75.6,76.1}; persistent grid regressed (85.6); explicit
// SW pipeline neutral (75.5); occupancy 43%..88% uncorrelated with perf.
// DRAM pinned ~81%, ~6.4 TB/s counted / ~7.1 TB/s effective on 512 MiB of
// irreducible zero-reuse traffic. Locked-in best: one-pass float4/thread,
// GRP=4 load/compute/store batches, streaming (.cs) hints, 4096x256 grid.

#define TT 16
#define BB 512
#define DD 8192
#define STRIDE4 ((BB * DD) / 4)   // float4 per timestep slab = 1,048,576
#define GRP 4

__global__ __launch_bounds__(256) void spike_kernel(
    const float4* __restrict__ in, float4* __restrict__ out)
{
    const unsigned idx = blockIdx.x * 256u + threadIdx.x;  // 0 .. STRIDE4-1
    const float4* __restrict__ p = in  + idx;
    float4*       __restrict__ q = out + idx;

    float4 V = make_float4(0.f, 0.f, 0.f, 0.f);
    float4 x[GRP];

#pragma unroll
    for (int g = 0; g < TT / GRP; ++g) {
        // Batch 4 streaming loads
#pragma unroll
        for (int t = 0; t < GRP; ++t)
            x[t] = __ldcs(p + (unsigned)(g * GRP + t) * STRIDE4);

        // Dependency chain in registers; overwrite x[] with outputs
#pragma unroll
        for (int t = 0; t < GRP; ++t) {
            V.x += x[t].x;  V.x = (fabsf(V.x) > 1.0f) ? 0.0f : V.x;
            V.y += x[t].y;  V.y = (fabsf(V.y) > 1.0f) ? 0.0f : V.y;
            V.z += x[t].z;  V.z = (fabsf(V.z) > 1.0f) ? 0.0f : V.z;
            V.w += x[t].w;  V.w = (fabsf(V.w) > 1.0f) ? 0.0f : V.w;
            x[t] = V;
        }

        // Batch 4 streaming stores
#pragma unroll
        for (int t = 0; t < GRP; ++t)
            __stcs(q + (unsigned)(g * GRP + t) * STRIDE4, x[t]);
    }
}

extern "C" void kernel_launch(void* const* d_in, const int* in_sizes, int n_in,
                              void* d_out, int out_size)
{
    (void)in_sizes; (void)n_in; (void)out_size;
    const float4* in  = (const float4*)d_in[0];
    float4*       out = (float4*)d_out;

    const int threads = 256;
    const int blocks  = STRIDE4 / threads;  // 4096
    spike_kernel<<<blocks, threads>>>(in, out);
}